// round 8
// baseline (speedup 1.0000x reference)
#include <cuda_runtime.h>

#define Bsz   128
#define Lseq  4096
#define Hd    64
#define G3    192
#define IN2H  128
#define NCLS  230
#define BL    (Bsz * Lseq)

typedef unsigned long long ull;

// Scratch (allocation-free rule: __device__ globals)
__device__ float g_gx[(size_t)2 * BL * G3];    // [dir][b][t][192]  (~805 MB)
__device__ float g_buf[(size_t)BL * IN2H];     // [b][t][128]       (~268 MB)

// ---------------- packed f32x2 / fast-math helpers ----------------
__device__ __forceinline__ ull fma2(ull a, ull b, ull c) {
    ull d;
    asm("fma.rn.f32x2 %0, %1, %2, %3;" : "=l"(d) : "l"(a), "l"(b), "l"(c));
    return d;
}
__device__ __forceinline__ float2 u2f2(ull v) {
    float2 f;
    asm("mov.b64 {%0, %1}, %2;" : "=f"(f.x), "=f"(f.y) : "l"(v));
    return f;
}
__device__ __forceinline__ float tanh_fast(float x) {
    float y;
    asm("tanh.approx.f32 %0, %1;" : "=f"(y) : "f"(x));
    return y;
}
__device__ __forceinline__ float sigm_fast(float x) {
    return fmaf(0.5f, tanh_fast(0.5f * x), 0.5f);
}
__device__ __forceinline__ unsigned smem_u32(const void* p) {
    return (unsigned)__cvta_generic_to_shared(p);
}
__device__ __forceinline__ void cp_async8(unsigned dst, const void* src) {
    asm volatile("cp.async.ca.shared.global [%0], [%1], 8;"
                 :: "r"(dst), "l"(src));
}
__device__ __forceinline__ void cp_commit() {
    asm volatile("cp.async.commit_group;");
}
template <int N>
__device__ __forceinline__ void cp_wait() {
    asm volatile("cp.async.wait_group %0;" :: "n"(N));
}

// ---------------- gx GEMM for layers 1..3 (unchanged from R7) -------------
__global__ void __launch_bounds__(256, 2)
gx_gemm_kernel(const float* __restrict__ w_ih,
               const float* __restrict__ b_ih,
               int layer) {
    const int d  = blockIdx.x & 1;
    const int c0 = (blockIdx.x >> 1) * 96;       // column half
    const size_t row0 = (size_t)blockIdx.y * 64;
    const int tid = threadIdx.x;
    const int tx = tid & 15;   // cols c0 + tx + 16*j, j<6
    const int ty = tid >> 4;   // rows ty + 16*i, i<4

    const ull* inp2 = (const ull*)g_buf;  // 64 ull per row
    const ull* w2g =
        (const ull*)(w_ih + ((size_t)(layer - 1) * 2 + d) * G3 * IN2H);

    __shared__ ull a_s[2][16][65];   // [buf][kpair][row]
    __shared__ ull b_s[2][16][97];   // [buf][kpair][col]
    const unsigned A_BUF_BYTES = 16 * 65 * 8;
    const unsigned B_BUF_BYTES = 16 * 97 * 8;

    unsigned a_dst[4], b_dst[6];
    const ull* a_src[4];
    const ull* b_src[6];
#pragma unroll
    for (int it = 0; it < 4; it++) {
        int lin = tid + it * 256;
        int r = lin >> 4, c2 = lin & 15;
        a_dst[it] = smem_u32(&a_s[0][c2][r]);
        a_src[it] = inp2 + (row0 + r) * 64 + c2;
    }
#pragma unroll
    for (int it = 0; it < 6; it++) {
        int lin = tid + it * 256;
        int cc = lin >> 4, c2 = lin & 15;
        b_dst[it] = smem_u32(&b_s[0][c2][cc]);
        b_src[it] = w2g + (size_t)(c0 + cc) * 64 + c2;
    }

    ull acc[4][6];
#pragma unroll
    for (int i = 0; i < 4; i++)
#pragma unroll
        for (int j = 0; j < 6; j++) acc[i][j] = 0ULL;

#pragma unroll
    for (int it = 0; it < 4; it++) cp_async8(a_dst[it], a_src[it]);
#pragma unroll
    for (int it = 0; it < 6; it++) cp_async8(b_dst[it], b_src[it]);
    cp_commit();

#pragma unroll
    for (int ch = 0; ch < 4; ch++) {
        const int buf = ch & 1;
        if (ch < 3) {
            const int nb = (ch + 1) & 1;
#pragma unroll
            for (int it = 0; it < 4; it++)
                cp_async8(a_dst[it] + nb * A_BUF_BYTES,
                          a_src[it] + (ch + 1) * 16);
#pragma unroll
            for (int it = 0; it < 6; it++)
                cp_async8(b_dst[it] + nb * B_BUF_BYTES,
                          b_src[it] + (ch + 1) * 16);
            cp_commit();
            cp_wait<1>();
        } else {
            cp_wait<0>();
        }
        __syncthreads();
#pragma unroll
        for (int kp = 0; kp < 16; kp++) {
            ull a2[4], b2[6];
#pragma unroll
            for (int i = 0; i < 4; i++) a2[i] = a_s[buf][kp][ty + 16 * i];
#pragma unroll
            for (int j = 0; j < 6; j++) b2[j] = b_s[buf][kp][tx + 16 * j];
#pragma unroll
            for (int i = 0; i < 4; i++)
#pragma unroll
                for (int j = 0; j < 6; j++)
                    acc[i][j] = fma2(a2[i], b2[j], acc[i][j]);
        }
        __syncthreads();
    }

    const float* bih = b_ih + ((size_t)layer * 2 + d) * G3;
#pragma unroll
    for (int i = 0; i < 4; i++) {
        size_t row = row0 + ty + 16 * i;
#pragma unroll
        for (int j = 0; j < 6; j++) {
            int c = c0 + tx + 16 * j;
            float2 f = u2f2(acc[i][j]);
            g_gx[((size_t)d * BL + row) * G3 + c] = f.x + f.y + bih[c];
        }
    }
}

// ---------------- sequential GRU scan (merged dirs, split-k) --------------
// One block per batch element, 384 threads = 12 warps (3/SMSP, balanced).
// Thread (half = tid/192, g = tid%192) computes the k-half [half*32, +32) of
// BOTH directions' dot products for gate-row g. Partials combined in shared.
// Gate phase: threads 0..63 -> dir0, 64..127 -> dir1.
__global__ void __launch_bounds__(384)
scan_kernel(const float* __restrict__ w_hh,
            const float* __restrict__ b_hh,
            const float* __restrict__ x,
            const float* __restrict__ w_ih0,
            const float* __restrict__ b_ih,
            int layer) {
    const int b = blockIdx.x;
    const int tid = threadIdx.x;
    const int half = tid / 192;
    const int g = tid % 192;

    const size_t base0 = ((size_t)layer * 2 + 0) * G3;
    const size_t base1 = ((size_t)layer * 2 + 1) * G3;
    const ull* W0 = (const ull*)w_hh + (base0 + g) * 32 + half * 16;
    const ull* W1 = (const ull*)w_hh + (base1 + g) * 32 + half * 16;
    ull w0[16], w1[16];
#pragma unroll
    for (int i = 0; i < 16; i++) { w0[i] = W0[i]; w1[i] = W1[i]; }
    const float bias0 = (half == 0) ? b_hh[base0 + g] : 0.0f;
    const float bias1 = (half == 0) ? b_hh[base1 + g] : 0.0f;

    __shared__ __align__(16) float h0_s[Hd];
    __shared__ __align__(16) float h1_s[Hd];
    __shared__ float ps0[2][G3];
    __shared__ float ps1[2][G3];
    __shared__ float gx0_s[G3];
    __shared__ float gx1_s[G3];
    if (tid < Hd) h0_s[tid] = 0.0f;
    else if (tid < 2 * Hd) h1_s[tid - Hd] = 0.0f;
    float hreg = 0.0f;  // dir0 comp for tid<64, dir1 comp for 64<=tid<128

    // gx stream: this thread feeds direction `half`, gate-row g
    const int dirD = half;
    const int t0 = dirD ? (Lseq - 1) : 0;
    const int tstep = dirD ? -1 : 1;
    const long gstep = (long)tstep * G3;
    float w0x = 0.0f, bi0 = 0.0f;
    const float* xs = nullptr;
    const float* gp = nullptr;
    if (layer == 0) {
        w0x = w_ih0[dirD * G3 + g];
        bi0 = b_ih[(size_t)dirD * G3 + g];
        xs = x + (size_t)b * Lseq + t0;
    } else {
        gp = g_gx + (((size_t)dirD * Bsz + b) * Lseq + t0) * G3 + g;
    }
    float* ob = g_buf + (size_t)b * Lseq * IN2H;

    __syncthreads();

    float q[4];
#pragma unroll
    for (int p = 0; p < 4; p++)
        q[p] = (layer == 0) ? xs[(long)p * tstep] : gp[(long)p * gstep];

    const ulonglong2* h40 = (const ulonglong2*)(h0_s + half * 32);
    const ulonglong2* h41 = (const ulonglong2*)(h1_s + half * 32);

#pragma unroll 1
    for (int s0 = 0; s0 < Lseq; s0 += 4) {
#pragma unroll
        for (int j = 0; j < 4; j++) {
            const int s = s0 + j;
            float raw = q[j];
            const int sp = s + 4;
            if (sp < Lseq)
                q[j] = (layer == 0) ? xs[(long)sp * tstep]
                                    : gp[(long)sp * gstep];
            float gxc = (layer == 0) ? fmaf(raw, w0x, bi0) : raw;

            // half-dots for both dirs: 2 chains each, depth 8
            ull a0 = 0, a1 = 0, c0 = 0, c1 = 0;
#pragma unroll
            for (int i = 0; i < 4; i++) {
                ulonglong2 u = h40[2 * i];
                ulonglong2 v = h40[2 * i + 1];
                a0 = fma2(w0[4 * i + 0], u.x, a0);
                a1 = fma2(w0[4 * i + 1], u.y, a1);
                a0 = fma2(w0[4 * i + 2], v.x, a0);
                a1 = fma2(w0[4 * i + 3], v.y, a1);
                ulonglong2 p2 = h41[2 * i];
                ulonglong2 r2 = h41[2 * i + 1];
                c0 = fma2(w1[4 * i + 0], p2.x, c0);
                c1 = fma2(w1[4 * i + 1], p2.y, c1);
                c0 = fma2(w1[4 * i + 2], r2.x, c0);
                c1 = fma2(w1[4 * i + 3], r2.y, c1);
            }
            float2 fa0 = u2f2(a0), fa1 = u2f2(a1);
            float2 fc0 = u2f2(c0), fc1 = u2f2(c1);
            ps0[half][g] = (fa0.x + fa0.y) + (fa1.x + fa1.y) + bias0;
            ps1[half][g] = (fc0.x + fc0.y) + (fc1.x + fc1.y) + bias1;
            if (half == 0) gx0_s[g] = gxc;
            else           gx1_s[g] = gxc;
            __syncthreads();

            if (tid < Hd) {
                const int j2 = tid;
                float ghr = ps0[0][j2] + ps0[1][j2];
                float ghz = ps0[0][Hd + j2] + ps0[1][Hd + j2];
                float ghn = ps0[0][2 * Hd + j2] + ps0[1][2 * Hd + j2];
                float r = sigm_fast(gx0_s[j2] + ghr);
                float z = sigm_fast(gx0_s[Hd + j2] + ghz);
                float n = tanh_fast(fmaf(r, ghn, gx0_s[2 * Hd + j2]));
                float hn = fmaf(z, hreg - n, n);
                hreg = hn;
                h0_s[j2] = hn;
                ob[(size_t)s * IN2H + j2] = hn;
            } else if (tid < 2 * Hd) {
                const int j2 = tid - Hd;
                float ghr = ps1[0][j2] + ps1[1][j2];
                float ghz = ps1[0][Hd + j2] + ps1[1][Hd + j2];
                float ghn = ps1[0][2 * Hd + j2] + ps1[1][2 * Hd + j2];
                float r = sigm_fast(gx1_s[j2] + ghr);
                float z = sigm_fast(gx1_s[Hd + j2] + ghz);
                float n = tanh_fast(fmaf(r, ghn, gx1_s[2 * Hd + j2]));
                float hn = fmaf(z, hreg - n, n);
                hreg = hn;
                h1_s[j2] = hn;
                ob[(size_t)(Lseq - 1 - s) * IN2H + Hd + j2] = hn;
            }
            __syncthreads();
        }
    }
}

// ---------------- final FC on last timestep ----------------
__global__ void fc_kernel(const float* __restrict__ fc_w,
                          const float* __restrict__ fc_b,
                          float* __restrict__ out) {
    int b = blockIdx.x;
    int c = threadIdx.x;
    __shared__ float last[IN2H];
    if (threadIdx.x < IN2H)
        last[threadIdx.x] =
            g_buf[((size_t)b * Lseq + (Lseq - 1)) * IN2H + threadIdx.x];
    __syncthreads();
    if (c < NCLS) {
        float s = fc_b[c];
        const float* w = fc_w + (size_t)c * IN2H;
#pragma unroll 8
        for (int k = 0; k < IN2H; k++) s += last[k] * w[k];
        out[(size_t)b * NCLS + c] = s;
    }
}

extern "C" void kernel_launch(void* const* d_in, const int* in_sizes, int n_in,
                              void* d_out, int out_size) {
    const float* x     = (const float*)d_in[0];
    const float* w_ih0 = (const float*)d_in[1];
    const float* w_ih  = (const float*)d_in[2];
    const float* w_hh  = (const float*)d_in[3];
    const float* b_ih  = (const float*)d_in[4];
    const float* b_hh  = (const float*)d_in[5];
    const float* fc_w  = (const float*)d_in[6];
    const float* fc_b  = (const float*)d_in[7];
    float* out = (float*)d_out;

    // Layer 0: gx fused into the scan (input size 1)
    scan_kernel<<<Bsz, 384>>>(w_hh, b_hh, x, w_ih0, b_ih, 0);
    // Layers 1..3: GEMM input projection, then scan
    for (int l = 1; l < 4; l++) {
        gx_gemm_kernel<<<dim3(4, BL / 64), 256>>>(w_ih, b_ih, l);
        scan_kernel<<<Bsz, 384>>>(w_hh, b_hh, x, w_ih0, b_ih, l);
    }
    fc_kernel<<<Bsz, 256>>>(fc_w, fc_b, out);
}

// round 9
// speedup vs baseline: 1.0487x; 1.0487x over previous
#include <cuda_runtime.h>

#define Bsz   128
#define Lseq  4096
#define Hd    64
#define G3    192
#define IN2H  128
#define NCLS  230
#define BL    (Bsz * Lseq)

typedef unsigned long long ull;

// Scratch (allocation-free rule: __device__ globals)
__device__ float g_gx[(size_t)2 * BL * G3];    // [dir][b][t][192]  (~805 MB)
__device__ float g_buf[(size_t)BL * IN2H];     // [b][t][128]       (~268 MB)

// ---------------- packed f32x2 / fast-math helpers ----------------
__device__ __forceinline__ ull fma2(ull a, ull b, ull c) {
    ull d;
    asm("fma.rn.f32x2 %0, %1, %2, %3;" : "=l"(d) : "l"(a), "l"(b), "l"(c));
    return d;
}
__device__ __forceinline__ float2 u2f2(ull v) {
    float2 f;
    asm("mov.b64 {%0, %1}, %2;" : "=f"(f.x), "=f"(f.y) : "l"(v));
    return f;
}
__device__ __forceinline__ float tanh_fast(float x) {
    float y;
    asm("tanh.approx.f32 %0, %1;" : "=f"(y) : "f"(x));
    return y;
}
__device__ __forceinline__ float sigm_fast(float x) {
    return fmaf(0.5f, tanh_fast(0.5f * x), 0.5f);
}
__device__ __forceinline__ unsigned smem_u32(const void* p) {
    return (unsigned)__cvta_generic_to_shared(p);
}
__device__ __forceinline__ void cp_async8(unsigned dst, const void* src) {
    asm volatile("cp.async.ca.shared.global [%0], [%1], 8;"
                 :: "r"(dst), "l"(src));
}
__device__ __forceinline__ void cp_commit() {
    asm volatile("cp.async.commit_group;");
}
template <int N>
__device__ __forceinline__ void cp_wait() {
    asm volatile("cp.async.wait_group %0;" :: "n"(N));
}

// ---------------- gx GEMM for layers 1..3 (frozen R7 version) -------------
__global__ void __launch_bounds__(256, 2)
gx_gemm_kernel(const float* __restrict__ w_ih,
               const float* __restrict__ b_ih,
               int layer) {
    const int d  = blockIdx.x & 1;
    const int c0 = (blockIdx.x >> 1) * 96;       // column half
    const size_t row0 = (size_t)blockIdx.y * 64;
    const int tid = threadIdx.x;
    const int tx = tid & 15;   // cols c0 + tx + 16*j, j<6
    const int ty = tid >> 4;   // rows ty + 16*i, i<4

    const ull* inp2 = (const ull*)g_buf;  // 64 ull per row
    const ull* w2g =
        (const ull*)(w_ih + ((size_t)(layer - 1) * 2 + d) * G3 * IN2H);

    __shared__ ull a_s[2][16][65];   // [buf][kpair][row]
    __shared__ ull b_s[2][16][97];   // [buf][kpair][col]
    const unsigned A_BUF_BYTES = 16 * 65 * 8;
    const unsigned B_BUF_BYTES = 16 * 97 * 8;

    unsigned a_dst[4], b_dst[6];
    const ull* a_src[4];
    const ull* b_src[6];
#pragma unroll
    for (int it = 0; it < 4; it++) {
        int lin = tid + it * 256;
        int r = lin >> 4, c2 = lin & 15;
        a_dst[it] = smem_u32(&a_s[0][c2][r]);
        a_src[it] = inp2 + (row0 + r) * 64 + c2;
    }
#pragma unroll
    for (int it = 0; it < 6; it++) {
        int lin = tid + it * 256;
        int cc = lin >> 4, c2 = lin & 15;
        b_dst[it] = smem_u32(&b_s[0][c2][cc]);
        b_src[it] = w2g + (size_t)(c0 + cc) * 64 + c2;
    }

    ull acc[4][6];
#pragma unroll
    for (int i = 0; i < 4; i++)
#pragma unroll
        for (int j = 0; j < 6; j++) acc[i][j] = 0ULL;

#pragma unroll
    for (int it = 0; it < 4; it++) cp_async8(a_dst[it], a_src[it]);
#pragma unroll
    for (int it = 0; it < 6; it++) cp_async8(b_dst[it], b_src[it]);
    cp_commit();

#pragma unroll
    for (int ch = 0; ch < 4; ch++) {
        const int buf = ch & 1;
        if (ch < 3) {
            const int nb = (ch + 1) & 1;
#pragma unroll
            for (int it = 0; it < 4; it++)
                cp_async8(a_dst[it] + nb * A_BUF_BYTES,
                          a_src[it] + (ch + 1) * 16);
#pragma unroll
            for (int it = 0; it < 6; it++)
                cp_async8(b_dst[it] + nb * B_BUF_BYTES,
                          b_src[it] + (ch + 1) * 16);
            cp_commit();
            cp_wait<1>();
        } else {
            cp_wait<0>();
        }
        __syncthreads();
#pragma unroll
        for (int kp = 0; kp < 16; kp++) {
            ull a2[4], b2[6];
#pragma unroll
            for (int i = 0; i < 4; i++) a2[i] = a_s[buf][kp][ty + 16 * i];
#pragma unroll
            for (int j = 0; j < 6; j++) b2[j] = b_s[buf][kp][tx + 16 * j];
#pragma unroll
            for (int i = 0; i < 4; i++)
#pragma unroll
                for (int j = 0; j < 6; j++)
                    acc[i][j] = fma2(a2[i], b2[j], acc[i][j]);
        }
        __syncthreads();
    }

    const float* bih = b_ih + ((size_t)layer * 2 + d) * G3;
#pragma unroll
    for (int i = 0; i < 4; i++) {
        size_t row = row0 + ty + 16 * i;
#pragma unroll
        for (int j = 0; j < 6; j++) {
            int c = c0 + tx + 16 * j;
            float2 f = u2f2(acc[i][j]);
            g_gx[((size_t)d * BL + row) * G3 + c] = f.x + f.y + bih[c];
        }
    }
}

// ---------------- sequential GRU scan ----------------
// One block per batch element, 384 threads = TWO INDEPENDENT 192-thread
// groups (d = tid/192), each running the R5 loop for its direction with a
// per-direction named barrier (bar.sync 1+d, 192). The groups never sync with
// each other, so one group's barrier/latency stalls are filled by the other
// group's FMA issue on the same SMSPs.
__global__ void __launch_bounds__(384)
scan_kernel(const float* __restrict__ w_hh,
            const float* __restrict__ b_hh,
            const float* __restrict__ x,
            const float* __restrict__ w_ih0,
            const float* __restrict__ b_ih,
            int layer) {
    const int b = blockIdx.x;
    const int tid = threadIdx.x;
    const int d = tid / 192;      // direction group
    const int g = tid % 192;      // gate row within group
    const unsigned barid = 1 + d;

    const float* W = w_hh + (((size_t)layer * 2 + d) * G3 + g) * Hd;
    ull w2[32];
#pragma unroll
    for (int i = 0; i < 32; i++) w2[i] = ((const ull*)W)[i];
    const float bias = b_hh[((size_t)layer * 2 + d) * G3 + g];

    __shared__ __align__(16) float h_s[2][Hd];
    __shared__ float gh_s[2][G3];
    __shared__ float gx_s[2][G3];
    if (g < Hd) h_s[d][g] = 0.0f;
    float hreg = 0.0f;

    const int t0 = (d == 0) ? 0 : (Lseq - 1);
    const int tstep = (d == 0) ? 1 : -1;

    float w0g = 0.0f, bi0 = 0.0f;
    const float* xs = nullptr;
    const float* gxp = nullptr;
    if (layer == 0) {
        w0g = w_ih0[d * G3 + g];
        bi0 = b_ih[(size_t)d * G3 + g];
        xs = x + (size_t)b * Lseq + t0;
    } else {
        gxp = g_gx + (((size_t)d * Bsz + b) * Lseq + t0) * G3 + g;
    }
    float* outp = g_buf + (size_t)b * Lseq * IN2H + d * Hd + g;
    const long gstep = (long)tstep * G3;

    asm volatile("bar.sync %0, %1;" :: "r"(barid), "r"(192) : "memory");

    float q[4];
#pragma unroll
    for (int j = 0; j < 4; j++)
        q[j] = (layer == 0) ? xs[(long)j * tstep] : gxp[(long)j * gstep];

#pragma unroll 1
    for (int s0 = 0; s0 < Lseq; s0 += 4) {
#pragma unroll
        for (int j = 0; j < 4; j++) {
            const int s = s0 + j;
            float raw = q[j];
            const int sp = s + 4;
            if (sp < Lseq)
                q[j] = (layer == 0) ? xs[(long)sp * tstep]
                                    : gxp[(long)sp * gstep];
            float gx_cur = (layer == 0) ? fmaf(raw, w0g, bi0) : raw;

            ull acc0 = 0ULL, acc1 = 0ULL, acc2 = 0ULL, acc3 = 0ULL;
            const ulonglong2* h4 = (const ulonglong2*)h_s[d];
#pragma unroll
            for (int i = 0; i < 8; i++) {
                ulonglong2 hv0 = h4[2 * i];
                ulonglong2 hv1 = h4[2 * i + 1];
                acc0 = fma2(w2[4 * i + 0], hv0.x, acc0);
                acc1 = fma2(w2[4 * i + 1], hv0.y, acc1);
                acc2 = fma2(w2[4 * i + 2], hv1.x, acc2);
                acc3 = fma2(w2[4 * i + 3], hv1.y, acc3);
            }
            float2 f0 = u2f2(acc0);
            float2 f1 = u2f2(acc1);
            float2 f2 = u2f2(acc2);
            float2 f3 = u2f2(acc3);
            float gh = ((f0.x + f0.y) + (f1.x + f1.y)) +
                       ((f2.x + f2.y) + (f3.x + f3.y)) + bias;

            gh_s[d][g] = gh;
            gx_s[d][g] = gx_cur;
            asm volatile("bar.sync %0, %1;" :: "r"(barid), "r"(192) : "memory");

            if (g < Hd) {
                float r = sigm_fast(gx_s[d][g] + gh_s[d][g]);
                float z = sigm_fast(gx_s[d][Hd + g] + gh_s[d][Hd + g]);
                float n = tanh_fast(
                    fmaf(r, gh_s[d][2 * Hd + g], gx_s[d][2 * Hd + g]));
                float hn = fmaf(z, hreg - n, n);  // (1-z)n + z*h
                hreg = hn;
                h_s[d][g] = hn;
                outp[(size_t)(t0 + s * tstep) * IN2H] = hn;
            }
            asm volatile("bar.sync %0, %1;" :: "r"(barid), "r"(192) : "memory");
        }
    }
}

// ---------------- final FC on last timestep ----------------
__global__ void fc_kernel(const float* __restrict__ fc_w,
                          const float* __restrict__ fc_b,
                          float* __restrict__ out) {
    int b = blockIdx.x;
    int c = threadIdx.x;
    __shared__ float last[IN2H];
    if (threadIdx.x < IN2H)
        last[threadIdx.x] =
            g_buf[((size_t)b * Lseq + (Lseq - 1)) * IN2H + threadIdx.x];
    __syncthreads();
    if (c < NCLS) {
        float s = fc_b[c];
        const float* w = fc_w + (size_t)c * IN2H;
#pragma unroll 8
        for (int k = 0; k < IN2H; k++) s += last[k] * w[k];
        out[(size_t)b * NCLS + c] = s;
    }
}

extern "C" void kernel_launch(void* const* d_in, const int* in_sizes, int n_in,
                              void* d_out, int out_size) {
    const float* x     = (const float*)d_in[0];
    const float* w_ih0 = (const float*)d_in[1];
    const float* w_ih  = (const float*)d_in[2];
    const float* w_hh  = (const float*)d_in[3];
    const float* b_ih  = (const float*)d_in[4];
    const float* b_hh  = (const float*)d_in[5];
    const float* fc_w  = (const float*)d_in[6];
    const float* fc_b  = (const float*)d_in[7];
    float* out = (float*)d_out;

    // Layer 0: gx fused into the scan (input size 1)
    scan_kernel<<<Bsz, 384>>>(w_hh, b_hh, x, w_ih0, b_ih, 0);
    // Layers 1..3: GEMM input projection, then scan
    for (int l = 1; l < 4; l++) {
        gx_gemm_kernel<<<dim3(4, BL / 64), 256>>>(w_ih, b_ih, l);
        scan_kernel<<<Bsz, 384>>>(w_hh, b_hh, x, w_ih0, b_ih, l);
    }
    fc_kernel<<<Bsz, 256>>>(fc_w, fc_b, out);
}